// round 15
// baseline (speedup 1.0000x reference)
#include <cuda_runtime.h>
#include <cstdint>

// VoxelHashTable — 2-kernel bin-append clustered gather.
//
// History: gather at byte-floor (183.7us @6.5TB/s) since R7; the counting
// sort pre-pass (hash+scan+scatter) costs a structural ~31us across plain
// launches (R8), persistent fusion (R9/R10 regressed), and PDL (R14 ~neutral).
// Fix: drop scan+scatter. hash_bin appends {qi,vidx} straight into fixed-
// capacity per-bin slot arrays (CAP=160 vs mean 117, sd~12); overflow and
// invalid entries go to a fallback list handled by dedicated gather warps,
// so CAP is performance-only, never correctness. Gather walks bins in
// ascending order -> same L2 dedup of duplicate rows. Replay reset is done
// by the last-finishing gather block (done-counter, no spin). 2 launches.

#define FEATURE_DIM 768
#define VEC4_PER_ROW (FEATURE_DIM / 4)     // 192
#define V4_PER_LANE (VEC4_PER_ROW / 32)    // 6
#define TABLE_MASK ((1u << 20) - 1u)
#define THREADS 256
#define M_MAX (1 << 18)                    // 262144 queries
#define BUCKET_SHIFT 7                     // 128 voxel rows per bin
#define NB_MAX 4096                        // bins (covers total_voxels<=2^19)
#define CAP 160                            // slots per bin (mean 117 + 3.5sd)
#define EXTRA_WARPS 8192                   // fallback list consumer warps

__device__ int2 g_slots[NB_MAX * CAP];     // {qi, vidx} per bin slot
__device__ int  g_count[NB_MAX];           // zero at load; gather tail resets
__device__ int2 g_extra[M_MAX];            // overflow / invalid fallback
__device__ int  g_extra_count;
__device__ int  g_done;

// K1: hash, table lookup, append to bin (or fallback list).
__global__ void __launch_bounds__(256) hash_bin(
    const float* __restrict__ query_pts,   // [M, 3]
    const int* __restrict__ buf,           // [2^20], int32
    int total_voxels)
{
    const int qi = blockIdx.x * blockDim.x + threadIdx.x;

    const float px = __ldg(&query_pts[qi * 3 + 0]);
    const float py = __ldg(&query_pts[qi * 3 + 1]);
    const float pz = __ldg(&query_pts[qi * 3 + 2]);

    // f32 division by 0.1f required for bit-exact floor(q / RES).
    const long long gx = (long long)floorf(px / 0.1f);
    const long long gy = (long long)floorf(py / 0.1f);
    const long long gz = (long long)floorf(pz / 0.1f);

    // Products ~1e10 overflow int32 -> 64-bit. Pow2 mod == AND (neg-safe).
    const unsigned h = (unsigned)((gx * 73856093LL + gy * 19349669LL
                                   + gz * 83492791LL) & (long long)TABLE_MASK);

    int v = __ldg(&buf[h]);
    if (v >= total_voxels) v = -1;

    if (v >= 0) {
        const int bin = v >> BUCKET_SHIFT;
        const int pos = atomicAdd(&g_count[bin], 1);
        if (pos < CAP) {
            g_slots[bin * CAP + pos] = make_int2(qi, v);
        } else {
            const int e = atomicAdd(&g_extra_count, 1);
            g_extra[e] = make_int2(qi, v);
        }
    } else {
        const int e = atomicAdd(&g_extra_count, 1);
        g_extra[e] = make_int2(qi, -1);
    }

    cudaTriggerProgrammaticLaunchCompletion();
}

__device__ __forceinline__ void copy_row(
    const float4* __restrict__ voxel_features, float4* __restrict__ out,
    int qi, int v, int lane)
{
    const float4* src = voxel_features + (size_t)v * VEC4_PER_ROW + lane;
    float4*       dst = out            + (size_t)qi * VEC4_PER_ROW + lane;

    float4 r[V4_PER_LANE];
    if (v >= 0) {
        #pragma unroll
        for (int i = 0; i < V4_PER_LANE; i++)   // 6 loads in flight (MLP=6)
            r[i] = __ldg(src + 32 * i);
    } else {
        #pragma unroll
        for (int i = 0; i < V4_PER_LANE; i++)
            r[i] = make_float4(0.f, 0.f, 0.f, 0.f);
    }

    // Streaming stores: output never re-read; keep L2 for feature rows.
    #pragma unroll
    for (int i = 0; i < V4_PER_LANE; i++)
        __stcs(dst + 32 * i, r[i]);
}

// K2: warp-per-slot gather, then last-finishing block resets replay state.
__global__ void __launch_bounds__(THREADS) gather_phase(
    const float4* __restrict__ voxel_features,  // [total_voxels, 192] as float4
    float4* __restrict__ out,                   // [M, 192] as float4
    int slot_warps)                             // NB * CAP
{
    cudaGridDependencySynchronize();            // K1's writes visible

    const int warp = threadIdx.x >> 5;
    const int lane = threadIdx.x & 31;
    const int wi   = blockIdx.x * (THREADS / 32) + warp;

    if (wi < slot_warps) {
        const int bin  = wi / CAP;
        const int slot = wi % CAP;
        int cnt = __ldg(&g_count[bin]);         // L2-hot broadcast
        if (cnt > CAP) cnt = CAP;
        if (slot < cnt) {
            const int2 s = __ldg(&g_slots[wi]); // wi == bin*CAP + slot
            copy_row(voxel_features, out, s.x, s.y, lane);
        }
    } else {
        // Fallback list: each warp strides over extras.
        const int j  = wi - slot_warps;         // 0 .. EXTRA_WARPS-1
        const int ec = __ldg(&g_extra_count);
        for (int k = j; k < ec; k += EXTRA_WARPS) {
            const int2 s = __ldg(&g_extra[k]);
            copy_row(voxel_features, out, s.x, s.y, lane);
        }
    }

    // Replay-state reset by the last-finishing block (no spinning).
    __shared__ int s_last;
    __syncthreads();
    if (threadIdx.x == 0) {
        __threadfence();
        s_last = (atomicAdd(&g_done, 1) == (int)gridDim.x - 1) ? 1 : 0;
    }
    __syncthreads();
    if (s_last) {
        for (int i = threadIdx.x; i < NB_MAX; i += THREADS)
            g_count[i] = 0;
        if (threadIdx.x == 0) {
            g_extra_count = 0;
            __threadfence();
            g_done = 0;
        }
    }
}

// PDL launch: downstream kernel starts early, self-gates via
// cudaGridDependencySynchronize().
template <typename... Args>
static void launch_pdl(void (*kernel)(Args...), dim3 grid, dim3 block, Args... args)
{
    cudaLaunchConfig_t cfg = {};
    cfg.gridDim  = grid;
    cfg.blockDim = block;
    cfg.dynamicSmemBytes = 0;
    cfg.stream = 0;
    cudaLaunchAttribute attr[1];
    attr[0].id = cudaLaunchAttributeProgrammaticStreamSerialization;
    attr[0].val.programmaticStreamSerializationAllowed = 1;
    cfg.attrs = attr;
    cfg.numAttrs = 1;
    cudaLaunchKernelEx(&cfg, kernel, args...);
}

extern "C" void kernel_launch(void* const* d_in, const int* in_sizes, int n_in,
                              void* d_out, int out_size)
{
    const float*  query_pts = (const float*)d_in[0];
    const float4* feats     = (const float4*)d_in[1];
    const int*    buf       = (const int*)d_in[2];
    float4*       out       = (float4*)d_out;

    const int M = in_sizes[0] / 3;                  // 262144
    const int total_voxels = in_sizes[1] / FEATURE_DIM;
    const int NB = (total_voxels + (1 << BUCKET_SHIFT) - 1) >> BUCKET_SHIFT;

    const int slot_warps  = NB * CAP;               // ~357k
    const int total_warps = slot_warps + EXTRA_WARPS;
    const int blocks      = (total_warps + (THREADS / 32) - 1) / (THREADS / 32);

    // hash_bin: NORMAL launch -> serializes against the previous replay's
    // gather (which resets g_count/g_extra_count/g_done at its tail).
    hash_bin<<<M / 256, 256>>>(query_pts, buf, total_voxels);

    launch_pdl(gather_phase, dim3(blocks), dim3(THREADS), feats, out, slot_warps);
}